// round 6
// baseline (speedup 1.0000x reference)
#include <cuda_runtime.h>
#include <math.h>

#define NB 8
#define NT 2048
#define NC 1024
#define NH 64
#define QSCALE 0.125f   // 64^-0.5
#define NTILES (NT / 64) // 32

// Scratch for projections.
__device__ float g_q[NB * NT * NH];
__device__ float g_k[NB * NT * NH];
__device__ float g_v[NB * NT * NH];

// ---------------------------------------------------------------------------
// Fused projection GEMM: {q,k,v} = x @ {wq,wk,wv}
// M = 16384, K = 1024, N = 192 (3x64). Block tile 128x192, thread tile 8x12.
// ---------------------------------------------------------------------------
#define PBK 16
#define PAP 132
#define PBP 196

__global__ __launch_bounds__(256) void proj_kernel(
    const float* __restrict__ x,
    const float* __restrict__ wq,
    const float* __restrict__ wk,
    const float* __restrict__ wv)
{
    __shared__ float sA[2][PBK][PAP];
    __shared__ float sB[2][PBK][PBP];

    const int m0  = blockIdx.x * 128;
    const int tid = threadIdx.x;
    const int tr  = tid >> 4;
    const int tc  = tid & 15;

    const float* wsel[3] = {wq, wk, wv};
    float*       dsel[3] = {g_q, g_k, g_v};

    float acc[8][12];
    #pragma unroll
    for (int i = 0; i < 8; i++)
        #pragma unroll
        for (int j = 0; j < 12; j++) acc[i][j] = 0.f;

    float4 ar[2], br[3];
    #pragma unroll
    for (int u = 0; u < 2; u++) {
        int f = tid * 2 + u;
        int r = f >> 2, c4 = f & 3;
        ar[u] = *(const float4*)&x[(size_t)(m0 + r) * NC + c4 * 4];
    }
    #pragma unroll
    for (int u = 0; u < 3; u++) {
        int f  = tid * 3 + u;
        int kk = f / 48, c4 = f % 48;
        int col = c4 * 4;
        br[u] = *(const float4*)&wsel[col >> 6][(size_t)kk * NH + (col & 63)];
    }
    #pragma unroll
    for (int u = 0; u < 2; u++) {
        int f = tid * 2 + u;
        int r = f >> 2, c4 = f & 3;
        sA[0][c4 * 4 + 0][r] = ar[u].x;
        sA[0][c4 * 4 + 1][r] = ar[u].y;
        sA[0][c4 * 4 + 2][r] = ar[u].z;
        sA[0][c4 * 4 + 3][r] = ar[u].w;
    }
    #pragma unroll
    for (int u = 0; u < 3; u++) {
        int f  = tid * 3 + u;
        int kk = f / 48, c4 = f % 48;
        *(float4*)&sB[0][kk][c4 * 4] = br[u];
    }
    __syncthreads();

    const int NSTEP = NC / PBK;
    for (int ks = 0; ks < NSTEP; ks++) {
        int cur = ks & 1;
        if (ks + 1 < NSTEP) {
            int k0 = (ks + 1) * PBK;
            #pragma unroll
            for (int u = 0; u < 2; u++) {
                int f = tid * 2 + u;
                int r = f >> 2, c4 = f & 3;
                ar[u] = *(const float4*)&x[(size_t)(m0 + r) * NC + k0 + c4 * 4];
            }
            #pragma unroll
            for (int u = 0; u < 3; u++) {
                int f  = tid * 3 + u;
                int kk = f / 48, c4 = f % 48;
                int col = c4 * 4;
                br[u] = *(const float4*)&wsel[col >> 6][(size_t)(k0 + kk) * NH + (col & 63)];
            }
        }
        #pragma unroll
        for (int kk = 0; kk < PBK; kk++) {
            float a[8], b[12];
            *(float4*)&a[0] = *(float4*)&sA[cur][kk][tr * 8];
            *(float4*)&a[4] = *(float4*)&sA[cur][kk][tr * 8 + 4];
            *(float4*)&b[0] = *(float4*)&sB[cur][kk][tc * 12];
            *(float4*)&b[4] = *(float4*)&sB[cur][kk][tc * 12 + 4];
            *(float4*)&b[8] = *(float4*)&sB[cur][kk][tc * 12 + 8];
            #pragma unroll
            for (int i = 0; i < 8; i++)
                #pragma unroll
                for (int j = 0; j < 12; j++)
                    acc[i][j] = fmaf(a[i], b[j], acc[i][j]);
        }
        if (ks + 1 < NSTEP) {
            int nxt = cur ^ 1;
            #pragma unroll
            for (int u = 0; u < 2; u++) {
                int f = tid * 2 + u;
                int r = f >> 2, c4 = f & 3;
                sA[nxt][c4 * 4 + 0][r] = ar[u].x;
                sA[nxt][c4 * 4 + 1][r] = ar[u].y;
                sA[nxt][c4 * 4 + 2][r] = ar[u].z;
                sA[nxt][c4 * 4 + 3][r] = ar[u].w;
            }
            #pragma unroll
            for (int u = 0; u < 3; u++) {
                int f  = tid * 3 + u;
                int kk = f / 48, c4 = f % 48;
                *(float4*)&sB[nxt][kk][c4 * 4] = br[u];
            }
        }
        __syncthreads();
    }

    #pragma unroll
    for (int i = 0; i < 8; i++) {
        int r = m0 + tr * 8 + i;
        #pragma unroll
        for (int g = 0; g < 3; g++) {
            int col = tc * 12 + g * 4;
            float* dst = dsel[col >> 6];
            float4 t = make_float4(acc[i][g*4+0], acc[i][g*4+1],
                                   acc[i][g*4+2], acc[i][g*4+3]);
            *(float4*)&dst[(size_t)r * NH + (col & 63)] = t;
        }
    }
}

// ---------------------------------------------------------------------------
// Causal flash attention v4b: paired query tiles share one KV stream.
// AP = 68 floats (272 B): row starts 16B-aligned for all float4 accesses.
// grid = (16, 8), 256 threads.
// ---------------------------------------------------------------------------
#define AP 68
struct AttnSmem {
    float qTh[64][AP];       // heavy Q transposed, pre-scaled
    float qTl[64][AP];       // light Q transposed, pre-scaled
    float kT [2][64][AP];    // K transposed, double-buffered
    float v  [2][64][AP];    // V natural, double-buffered
    float sTh[64][AP];       // heavy P transposed: sTh[col][row]
    float sTl[64][AP];       // light P transposed
};

extern __shared__ char attn_smem_raw[];

template<bool BOTH>
__device__ __forceinline__ void kv_step(
    AttnSmem* sm, int cur, bool maskH, bool maskL, int ty, int tx,
    float (&o)[8][4], float (&m)[8], float (&l)[8])
{
    const int NR = BOTH ? 8 : 4;

    // ---- S = Q @ K^T ----
    float acc[8][4];
    #pragma unroll
    for (int i = 0; i < NR; i++)
        #pragma unroll
        for (int j = 0; j < 4; j++) acc[i][j] = 0.f;

    #pragma unroll
    for (int kk = 0; kk < 64; kk++) {
        float4 b4 = *(float4*)&sm->kT[cur][kk][tx * 4];
        float bv[4] = {b4.x, b4.y, b4.z, b4.w};
        float4 a4 = *(float4*)&sm->qTh[kk][ty * 4];
        float av[4] = {a4.x, a4.y, a4.z, a4.w};
        #pragma unroll
        for (int i = 0; i < 4; i++)
            #pragma unroll
            for (int j = 0; j < 4; j++)
                acc[i][j] = fmaf(av[i], bv[j], acc[i][j]);
        if (BOTH) {
            float4 c4 = *(float4*)&sm->qTl[kk][ty * 4];
            float cv[4] = {c4.x, c4.y, c4.z, c4.w};
            #pragma unroll
            for (int i = 0; i < 4; i++)
                #pragma unroll
                for (int j = 0; j < 4; j++)
                    acc[4 + i][j] = fmaf(cv[i], bv[j], acc[4 + i][j]);
        }
    }

    if (maskH) {
        #pragma unroll
        for (int i = 0; i < 4; i++)
            #pragma unroll
            for (int j = 0; j < 4; j++)
                if (tx * 4 + j > ty * 4 + i) acc[i][j] = -INFINITY;
    }
    if (BOTH && maskL) {
        #pragma unroll
        for (int i = 0; i < 4; i++)
            #pragma unroll
            for (int j = 0; j < 4; j++)
                if (tx * 4 + j > ty * 4 + i) acc[4 + i][j] = -INFINITY;
    }

    // ---- online softmax (row reductions over 16 tx lanes) ----
    float pr[8][4];
    #pragma unroll
    for (int i = 0; i < NR; i++) {
        float mv = fmaxf(fmaxf(acc[i][0], acc[i][1]),
                         fmaxf(acc[i][2], acc[i][3]));
        #pragma unroll
        for (int d = 1; d < 16; d <<= 1)
            mv = fmaxf(mv, __shfl_xor_sync(0xffffffffu, mv, d));
        float mn = fmaxf(m[i], mv);
        float alpha = __expf(m[i] - mn);
        m[i] = mn;
        float rs = 0.f;
        #pragma unroll
        for (int j = 0; j < 4; j++) {
            pr[i][j] = __expf(acc[i][j] - mn);
            rs += pr[i][j];
        }
        #pragma unroll
        for (int d = 1; d < 16; d <<= 1)
            rs += __shfl_xor_sync(0xffffffffu, rs, d);
        l[i] = l[i] * alpha + rs;
        #pragma unroll
        for (int j = 0; j < 4; j++) o[i][j] *= alpha;
    }

    // ---- stage P transposed (half-warp local) ----
    #pragma unroll
    for (int j = 0; j < 4; j++) {
        *(float4*)&sm->sTh[tx * 4 + j][ty * 4] =
            make_float4(pr[0][j], pr[1][j], pr[2][j], pr[3][j]);
        if (BOTH)
            *(float4*)&sm->sTl[tx * 4 + j][ty * 4] =
                make_float4(pr[4][j], pr[5][j], pr[6][j], pr[7][j]);
    }
    __syncwarp();

    // ---- O += P @ V ----
    #pragma unroll
    for (int kk = 0; kk < 64; kk++) {
        float4 vv4 = *(float4*)&sm->v[cur][kk][tx * 4];
        float vv[4] = {vv4.x, vv4.y, vv4.z, vv4.w};
        float4 p4 = *(float4*)&sm->sTh[kk][ty * 4];
        float pv[4] = {p4.x, p4.y, p4.z, p4.w};
        #pragma unroll
        for (int i = 0; i < 4; i++)
            #pragma unroll
            for (int j = 0; j < 4; j++)
                o[i][j] = fmaf(pv[i], vv[j], o[i][j]);
        if (BOTH) {
            float4 q4 = *(float4*)&sm->sTl[kk][ty * 4];
            float qv[4] = {q4.x, q4.y, q4.z, q4.w};
            #pragma unroll
            for (int i = 0; i < 4; i++)
                #pragma unroll
                for (int j = 0; j < 4; j++)
                    o[4 + i][j] = fmaf(qv[i], vv[j], o[4 + i][j]);
        }
    }
}

__global__ __launch_bounds__(256) void attn_kernel(float* __restrict__ out)
{
    AttnSmem* sm = reinterpret_cast<AttnSmem*>(attn_smem_raw);

    const int b   = blockIdx.y;
    const int p   = blockIdx.x;          // pair index 0..15
    const int ih  = NTILES - 1 - p;      // heavy query tile
    const int il  = p;                   // light query tile
    const int tid = threadIdx.x;
    const int ty  = tid >> 4;
    const int tx  = tid & 15;

    const float* Qb = g_q + (size_t)b * NT * NH;
    const float* Kb = g_k + (size_t)b * NT * NH;
    const float* Vb = g_v + (size_t)b * NT * NH;

    // ---- load both Q tiles transposed, pre-scaled ----
    #pragma unroll
    for (int u = 0; u < 4; u++) {
        int f  = tid * 4 + u;
        int r  = f >> 4;
        int c4 = f & 15;
        float4 th = *(const float4*)&Qb[(size_t)(ih * 64 + r) * NH + c4 * 4];
        float4 tl = *(const float4*)&Qb[(size_t)(il * 64 + r) * NH + c4 * 4];
        sm->qTh[c4 * 4 + 0][r] = th.x * QSCALE;
        sm->qTh[c4 * 4 + 1][r] = th.y * QSCALE;
        sm->qTh[c4 * 4 + 2][r] = th.z * QSCALE;
        sm->qTh[c4 * 4 + 3][r] = th.w * QSCALE;
        sm->qTl[c4 * 4 + 0][r] = tl.x * QSCALE;
        sm->qTl[c4 * 4 + 1][r] = tl.y * QSCALE;
        sm->qTl[c4 * 4 + 2][r] = tl.z * QSCALE;
        sm->qTl[c4 * 4 + 3][r] = tl.w * QSCALE;
    }
    // ---- KV tile 0 into buffer 0 ----
    #pragma unroll
    for (int u = 0; u < 4; u++) {
        int f  = tid * 4 + u;
        int r  = f >> 4;
        int c4 = f & 15;
        size_t gb = (size_t)r * NH + c4 * 4;
        float4 tk = *(const float4*)&Kb[gb];
        float4 tv = *(const float4*)&Vb[gb];
        sm->kT[0][c4 * 4 + 0][r] = tk.x;
        sm->kT[0][c4 * 4 + 1][r] = tk.y;
        sm->kT[0][c4 * 4 + 2][r] = tk.z;
        sm->kT[0][c4 * 4 + 3][r] = tk.w;
        *(float4*)&sm->v[0][r][c4 * 4] = tv;
    }
    __syncthreads();

    float o[8][4];
    float m[8], l[8];
    #pragma unroll
    for (int i = 0; i < 8; i++) {
        m[i] = -INFINITY; l[i] = 0.f;
        #pragma unroll
        for (int j = 0; j < 4; j++) o[i][j] = 0.f;
    }

    for (int jt = 0; jt <= ih; jt++) {
        int cur = jt & 1;
        // prefetch next KV tile into registers
        float4 kr[4], vr[4];
        if (jt < ih) {
            #pragma unroll
            for (int u = 0; u < 4; u++) {
                int f  = tid * 4 + u;
                int r  = f >> 4;
                int c4 = f & 15;
                size_t gb = (size_t)((jt + 1) * 64 + r) * NH + c4 * 4;
                kr[u] = *(const float4*)&Kb[gb];
                vr[u] = *(const float4*)&Vb[gb];
            }
        }

        if (jt <= il) kv_step<true >(sm, cur, jt == ih, jt == il, ty, tx, o, m, l);
        else          kv_step<false>(sm, cur, jt == ih, false,    ty, tx, o, m, l);

        if (jt < ih) {
            int nxt = cur ^ 1;
            #pragma unroll
            for (int u = 0; u < 4; u++) {
                int f  = tid * 4 + u;
                int r  = f >> 4;
                int c4 = f & 15;
                sm->kT[nxt][c4 * 4 + 0][r] = kr[u].x;
                sm->kT[nxt][c4 * 4 + 1][r] = kr[u].y;
                sm->kT[nxt][c4 * 4 + 2][r] = kr[u].z;
                sm->kT[nxt][c4 * 4 + 3][r] = kr[u].w;
                *(float4*)&sm->v[nxt][r][c4 * 4] = vr[u];
            }
        }
        __syncthreads();
    }

    // ---- normalize and write both tiles ----
    #pragma unroll
    for (int i = 0; i < 4; i++) {
        float inv = 1.f / l[i];
        float4 t = make_float4(o[i][0] * inv, o[i][1] * inv,
                               o[i][2] * inv, o[i][3] * inv);
        size_t row = (size_t)b * NT + ih * 64 + ty * 4 + i;
        *(float4*)&out[row * NH + tx * 4] = t;
    }
    #pragma unroll
    for (int i = 0; i < 4; i++) {
        float inv = 1.f / l[4 + i];
        float4 t = make_float4(o[4+i][0] * inv, o[4+i][1] * inv,
                               o[4+i][2] * inv, o[4+i][3] * inv);
        size_t row = (size_t)b * NT + il * 64 + ty * 4 + i;
        *(float4*)&out[row * NH + tx * 4] = t;
    }
}

// ---------------------------------------------------------------------------

extern "C" void kernel_launch(void* const* d_in, const int* in_sizes, int n_in,
                              void* d_out, int out_size)
{
    const float* x  = (const float*)d_in[0];
    const float* wq = (const float*)d_in[1];
    const float* wk = (const float*)d_in[2];
    const float* wv = (const float*)d_in[3];
    float* out = (float*)d_out;

    const int smem_bytes = (int)sizeof(AttnSmem);
    cudaFuncSetAttribute(attn_kernel,
                         cudaFuncAttributeMaxDynamicSharedMemorySize,
                         smem_bytes);

    proj_kernel<<<dim3((NB * NT) / 128), 256>>>(x, wq, wk, wv);
    attn_kernel<<<dim3(NTILES / 2, NB), 256, smem_bytes>>>(out);
}